// round 4
// baseline (speedup 1.0000x reference)
#include <cuda_runtime.h>

#define B_ROWS 32768
#define D_IN   200
#define K_SAMP 10
#define NCHUNK 4
#define CHUNK  (B_ROWS / NCHUNK)   // 8192
#define TM     64
#define APAD   68
#define MLP_THREADS 512

// logits scratch
__device__ float g_logits[(size_t)B_ROWS * D_IN];

// smem layout (floats)
#define OFF_X  0                      // XsT[200][68]; reused as H2T after layer2
#define OFF_H1 (200 * APAD)           // H1T[100][68]
#define OFF_WS (OFF_H1 + 100 * APAD)  // weight chunk, max 128*20 = 2560
#define SMEM_FLOATS (OFF_WS + 2560)   // 22960 floats = 91840 B

typedef unsigned long long ull;

__device__ __forceinline__ ull dup2(float w) {
    ull r; asm("mov.b64 %0, {%1, %1};" : "=l"(r) : "f"(w)); return r;
}
__device__ __forceinline__ ull fma2(ull a, ull b, ull c) {
    ull d; asm("fma.rn.f32x2 %0, %1, %2, %3;" : "=l"(d) : "l"(a), "l"(b), "l"(c)); return d;
}
__device__ __forceinline__ void unpack2(ull v, float& lo, float& hi) {
    asm("mov.b64 {%0, %1}, %2;" : "=f"(lo), "=f"(hi) : "l"(v));
}
__device__ __forceinline__ float frcp(float x) {
    float r; asm("rcp.approx.f32 %0, %1;" : "=f"(r) : "f"(x)); return r;
}

// ---- one GEMM layer over 64 rows; A in smem [K][APAD]; 512 threads, 4 rows/warp ----
template <int K, int N, int CI, int BK, bool RELU, bool TOGLOBAL>
__device__ __forceinline__ void layer(float* smem, const float* Asm,
                                      const float* __restrict__ Wg,
                                      const float* __restrict__ bg,
                                      float* Hsm, float* __restrict__ Gout,
                                      int tid) {
    constexpr int KSTEP = (BK % 4 == 0) ? 4 : 2;
    constexpr int NLD = (BK * N + MLP_THREADS - 1) / MLP_THREADS;
    float* ws = smem + OFF_WS;
    const int lane = tid & 31;
    const int wy = tid >> 5;  // 0..15, rows [4wy, 4wy+4)

    ull acc[2][CI];
#pragma unroll
    for (int r = 0; r < 2; r++)
#pragma unroll
        for (int c = 0; c < CI; c++) acc[r][c] = 0ull;

    float pf[NLD];
#pragma unroll
    for (int i = 0; i < NLD; i++) {
        int idx = tid + MLP_THREADS * i;
        if (idx < BK * N) pf[i] = Wg[idx];
    }
    __syncthreads();
#pragma unroll
    for (int i = 0; i < NLD; i++) {
        int idx = tid + MLP_THREADS * i;
        if (idx < BK * N) { int kk = idx / N, c = idx - kk * N; ws[c * BK + kk] = pf[i]; }
    }
    __syncthreads();

    for (int k0 = 0; k0 < K; k0 += BK) {
        const bool more = (k0 + BK) < K;
        if (more) {
            const float* wn = Wg + (size_t)(k0 + BK) * N;
#pragma unroll
            for (int i = 0; i < NLD; i++) {
                int idx = tid + MLP_THREADS * i;
                if (idx < BK * N) pf[i] = wn[idx];
            }
        }
        const float* abase = Asm + k0 * APAD + wy * 4;
#pragma unroll
        for (int kk = 0; kk < BK; kk += KSTEP) {
            float wv[CI][KSTEP];
#pragma unroll
            for (int c = 0; c < CI; c++) {
                const float* wp_ = &ws[(lane + 32 * c) * BK + kk];
                if (KSTEP == 4) {
                    float4 v = *(const float4*)wp_;
                    wv[c][0] = v.x; wv[c][1] = v.y; wv[c][2] = v.z; wv[c][3] = v.w;
                } else {
                    float2 v = *(const float2*)wp_;
                    wv[c][0] = v.x; wv[c][1] = v.y;
                }
            }
#pragma unroll
            for (int j = 0; j < KSTEP; j++) {
                ulonglong2 a = *(const ulonglong2*)(abase + (kk + j) * APAD);
#pragma unroll
                for (int c = 0; c < CI; c++) {
                    ull wp = dup2(wv[c][j]);
                    acc[0][c] = fma2(a.x, wp, acc[0][c]);
                    acc[1][c] = fma2(a.y, wp, acc[1][c]);
                }
            }
        }
        if (more) {
            __syncthreads();
#pragma unroll
            for (int i = 0; i < NLD; i++) {
                int idx = tid + MLP_THREADS * i;
                if (idx < BK * N) { int kk = idx / N, c = idx - kk * N; ws[c * BK + kk] = pf[i]; }
            }
            __syncthreads();
        }
    }

#pragma unroll
    for (int c = 0; c < CI; c++) {
        int col = lane + 32 * c;
        if (col < N) {
            float bv = bg[col];
#pragma unroll
            for (int r = 0; r < 2; r++) {
                float lo, hi;
                unpack2(acc[r][c], lo, hi);
                lo += bv; hi += bv;
                if (RELU) { lo = fmaxf(lo, 0.0f); hi = fmaxf(hi, 0.0f); }
                int row = wy * 4 + 2 * r;
                if (TOGLOBAL) {
                    Gout[(size_t)row * N + col] = lo;
                    Gout[(size_t)(row + 1) * N + col] = hi;
                } else {
                    *(float2*)&Hsm[col * APAD + row] = make_float2(lo, hi);
                }
            }
        }
    }
}

__global__ __launch_bounds__(MLP_THREADS, 2) void mlp_kernel(
    const float* __restrict__ x,
    const float* __restrict__ w1, const float* __restrict__ b1,
    const float* __restrict__ w2, const float* __restrict__ b2,
    const float* __restrict__ wl, const float* __restrict__ bl,
    float* __restrict__ logits) {
    extern __shared__ float smem[];
    const int tid = threadIdx.x;
    const int rowBase = blockIdx.x * TM;

    // stage x transposed: XsT[k][row]
    {
        const float4* xb = (const float4*)(x + (size_t)rowBase * D_IN);
        for (int it = tid; it < 64 * 50; it += MLP_THREADS) {
            int q = it >> 6, row = it & 63;
            float4 v = xb[row * 50 + q];
            float* p = smem + OFF_X + (4 * q) * APAD + row;
            p[0] = v.x; p[APAD] = v.y; p[2 * APAD] = v.z; p[3 * APAD] = v.w;
        }
    }
    layer<200, 100, 4, 20, true, false>(smem, smem + OFF_X, w1, b1, smem + OFF_H1, nullptr, tid);
    layer<100, 100, 4, 20, true, false>(smem, smem + OFF_H1, w2, b2, smem + OFF_X, nullptr, tid);
    layer<100, 200, 7, 10, false, true>(smem, smem + OFF_X, wl, bl, nullptr,
                                        logits + (size_t)rowBase * D_IN, tid);
}

// ---- sampler: one warp per row, 8 contiguous elems per lane (lanes 0..24) ----
__device__ __forceinline__ void load8(float* dst, const float* src, bool act) {
    if (act) {
        float4 a = *(const float4*)src;
        float4 b = *(const float4*)(src + 4);
        dst[0] = a.x; dst[1] = a.y; dst[2] = a.z; dst[3] = a.w;
        dst[4] = b.x; dst[5] = b.y; dst[6] = b.z; dst[7] = b.w;
    } else {
#pragma unroll
        for (int i = 0; i < 8; i++) dst[i] = 0.5f;
    }
}

__global__ __launch_bounds__(256, 4) void sample_kernel(
    const float* __restrict__ x, const float* __restrict__ uniform,
    const float* __restrict__ logits,
    const float* __restrict__ wo, const float* __restrict__ bo,
    float* __restrict__ preds, float* __restrict__ samples) {
    const int b = (blockIdx.x * 256 + threadIdx.x) >> 5;  // chunk-local row
    const int lane = threadIdx.x & 31;
    const bool act = lane < 25;
    const int d0 = 8 * lane;
    constexpr float EPSF = 1.1920929e-07f;

    float E[8], smp[8];
    {
        float lg[8];
        if (act) load8(lg, &logits[(size_t)b * D_IN + d0], true);
        else {
#pragma unroll
            for (int i = 0; i < 8; i++) lg[i] = -1e30f;
        }
        float m = lg[0];
#pragma unroll
        for (int i = 1; i < 8; i++) m = fmaxf(m, lg[i]);
#pragma unroll
        for (int off = 16; off > 0; off >>= 1)
            m = fmaxf(m, __shfl_xor_sync(0xffffffffu, m, off));
#pragma unroll
        for (int i = 0; i < 8; i++) {
            E[i] = act ? __expf(2.0f * (lg[i] - m)) : 0.0f;
            smp[i] = 0.0f;
        }
    }

    const float* up = uniform + (size_t)b * (K_SAMP * D_IN) + d0;
    float cu[8];
    load8(cu, up, act);

#pragma unroll
    for (int k = 0; k < K_SAMP; k++) {
        float nu[8];
        if (k < K_SAMP - 1) load8(nu, up + (k + 1) * D_IN, act);
        float s = 0.0f;
#pragma unroll
        for (int i = 0; i < 8; i++) {
            float u = fmaxf(cu[i], EPSF);
            float tl = -__logf(u);
            float xm = u - 1.0f;
            float tp = xm * fmaf(xm, fmaf(xm, -0.33333333f, 0.5f), -1.0f);
            float t = (u > 0.99f) ? tp : tl;
            float r = frcp(t);
            float w = E[i] * r * r;   // exp(2(lg-m)) / t^2
            cu[i] = w;                // reuse buffer
            s += w;
        }
#pragma unroll
        for (int off = 16; off > 0; off >>= 1)
            s += __shfl_xor_sync(0xffffffffu, s, off);
        float inv = frcp(s);
#pragma unroll
        for (int i = 0; i < 8; i++) smp[i] = fmaxf(smp[i], cu[i] * inv);
        if (k < K_SAMP - 1) {
#pragma unroll
            for (int i = 0; i < 8; i++) cu[i] = nu[i];
        }
    }

    if (act) {
        *(float4*)&samples[(size_t)b * D_IN + d0] =
            make_float4(smp[0], smp[1], smp[2], smp[3]);
        *(float4*)&samples[(size_t)b * D_IN + d0 + 4] =
            make_float4(smp[4], smp[5], smp[6], smp[7]);
    }

    // preds head
    float p0 = 0.0f, p1 = 0.0f;
    if (act) {
        float xv[8];
        load8(xv, &x[(size_t)b * D_IN + d0], true);
#pragma unroll
        for (int i = 0; i < 8; i += 2) {
            float4 w4 = *(const float4*)&wo[(d0 + i) * 2];
            float a0 = xv[i] * smp[i], a1 = xv[i + 1] * smp[i + 1];
            p0 += a0 * w4.x + a1 * w4.z;
            p1 += a0 * w4.y + a1 * w4.w;
        }
    }
#pragma unroll
    for (int off = 16; off > 0; off >>= 1) {
        p0 += __shfl_xor_sync(0xffffffffu, p0, off);
        p1 += __shfl_xor_sync(0xffffffffu, p1, off);
    }
    if (lane == 0) {
        p0 += bo[0]; p1 += bo[1];
        float mm = fmaxf(p0, p1);
        float e0 = __expf(p0 - mm), e1 = __expf(p1 - mm);
        float is = 1.0f / (e0 + e1);
        preds[(size_t)b * 2 + 0] = e0 * is;
        preds[(size_t)b * 2 + 1] = e1 * is;
    }
}

// ---- stream/event context (created once, host-side; no device memory) ----
struct Ctx {
    cudaStream_t sA, sB;
    cudaEvent_t eFork, eM[NCHUNK], eJA, eJB;
    Ctx() {
        cudaStreamCreateWithFlags(&sA, cudaStreamNonBlocking);
        cudaStreamCreateWithFlags(&sB, cudaStreamNonBlocking);
        cudaEventCreateWithFlags(&eFork, cudaEventDisableTiming);
        for (int i = 0; i < NCHUNK; i++)
            cudaEventCreateWithFlags(&eM[i], cudaEventDisableTiming);
        cudaEventCreateWithFlags(&eJA, cudaEventDisableTiming);
        cudaEventCreateWithFlags(&eJB, cudaEventDisableTiming);
    }
};

extern "C" void kernel_launch(void* const* d_in, const int* in_sizes, int n_in,
                              void* d_out, int out_size) {
    static Ctx ctx;  // one-time resource init (identical work every call)

    const float* x  = (const float*)d_in[0];
    const float* un = (const float*)d_in[1];
    const float* w1 = (const float*)d_in[2];
    const float* b1 = (const float*)d_in[3];
    const float* w2 = (const float*)d_in[4];
    const float* b2 = (const float*)d_in[5];
    const float* wl = (const float*)d_in[6];
    const float* bl = (const float*)d_in[7];
    const float* wo = (const float*)d_in[8];
    const float* bo = (const float*)d_in[9];
    float* out = (float*)d_out;

    float* lgts;
    cudaGetSymbolAddress((void**)&lgts, g_logits);

    const int smem_bytes = SMEM_FLOATS * (int)sizeof(float);  // 91840
    cudaFuncSetAttribute(mlp_kernel, cudaFuncAttributeMaxDynamicSharedMemorySize, smem_bytes);

    // fork both worker streams off the capture-origin (legacy) stream
    cudaEventRecord(ctx.eFork, 0);
    cudaStreamWaitEvent(ctx.sA, ctx.eFork, 0);
    cudaStreamWaitEvent(ctx.sB, ctx.eFork, 0);

    for (int c = 0; c < NCHUNK; c++) {
        const size_t ro = (size_t)c * CHUNK;
        mlp_kernel<<<CHUNK / TM, MLP_THREADS, smem_bytes, ctx.sA>>>(
            x + ro * D_IN, w1, b1, w2, b2, wl, bl, lgts + ro * D_IN);
        cudaEventRecord(ctx.eM[c], ctx.sA);
        cudaStreamWaitEvent(ctx.sB, ctx.eM[c], 0);
        sample_kernel<<<CHUNK / 8, 256, 0, ctx.sB>>>(
            x + ro * D_IN, un + ro * (K_SAMP * D_IN), lgts + ro * D_IN, wo, bo,
            out + ro * 2, out + (size_t)B_ROWS * 2 + ro * D_IN);
    }

    // join both streams back into the origin stream
    cudaEventRecord(ctx.eJA, ctx.sA);
    cudaStreamWaitEvent(0, ctx.eJA, 0);
    cudaEventRecord(ctx.eJB, ctx.sB);
    cudaStreamWaitEvent(0, ctx.eJB, 0);
}

// round 5
// speedup vs baseline: 1.3763x; 1.3763x over previous
#include <cuda_runtime.h>

#define B_ROWS 32768
#define D_IN   200
#define K_SAMP 10
#define NCHUNK 2
#define CHUNK  (B_ROWS / NCHUNK)   // 16384
#define TM     32
#define APAD   36

// logits scratch
__device__ float g_logits[(size_t)B_ROWS * D_IN];

// smem (floats): XsT[200][36] | H1T[100][36] (layer2 writes in place) | WS 2560
#define OFF_X  0
#define OFF_H1 (200 * APAD)                  // 7200
#define OFF_WS (OFF_H1 + 100 * APAD)         // 10800
#define SMEM_FLOATS (OFF_WS + 2560)          // 13360 -> 53440 B

typedef unsigned long long ull;

__device__ __forceinline__ ull dup2(float w) {
    ull r; asm("mov.b64 %0, {%1, %1};" : "=l"(r) : "f"(w)); return r;
}
__device__ __forceinline__ ull fma2(ull a, ull b, ull c) {
    ull d; asm("fma.rn.f32x2 %0, %1, %2, %3;" : "=l"(d) : "l"(a), "l"(b), "l"(c)); return d;
}
__device__ __forceinline__ void unpack2(ull v, float& lo, float& hi) {
    asm("mov.b64 {%0, %1}, %2;" : "=f"(lo), "=f"(hi) : "l"(v));
}
__device__ __forceinline__ float frcp(float x) {
    float r; asm("rcp.approx.f32 %0, %1;" : "=f"(r) : "f"(x)); return r;
}

// ---- one layer over 32 rows; A in smem [K][APAD]; 8 warps x 4 rows ----
template <int K, int N, int CI, int BK, bool RELU, bool TOGLOBAL>
__device__ __forceinline__ void layer(float* smem, const float* Asm,
                                      const float* __restrict__ Wg,
                                      const float* __restrict__ bg,
                                      float* Hsm, float* __restrict__ Gout,
                                      int tid) {
    constexpr int KSTEP = (BK % 4 == 0) ? 4 : 2;
    constexpr int NLD = (BK * N + 255) / 256;
    float* ws = smem + OFF_WS;                 // ws[col*BK + kk]
    const int lane = tid & 31;
    const int wy = tid >> 5;                   // rows [4wy, 4wy+4)

    ull acc[2][CI];
#pragma unroll
    for (int r = 0; r < 2; r++)
#pragma unroll
        for (int c = 0; c < CI; c++) acc[r][c] = 0ull;

    float pf[NLD];
#pragma unroll
    for (int i = 0; i < NLD; i++) {
        int idx = tid + 256 * i;
        if (idx < BK * N) pf[i] = Wg[idx];
    }
    __syncthreads();
#pragma unroll
    for (int i = 0; i < NLD; i++) {
        int idx = tid + 256 * i;
        if (idx < BK * N) { int kk = idx / N, c = idx - kk * N; ws[c * BK + kk] = pf[i]; }
    }
    __syncthreads();

    for (int k0 = 0; k0 < K; k0 += BK) {
        const bool more = (k0 + BK) < K;
        if (more) {
            const float* wn = Wg + (size_t)(k0 + BK) * N;
#pragma unroll
            for (int i = 0; i < NLD; i++) {
                int idx = tid + 256 * i;
                if (idx < BK * N) pf[i] = wn[idx];
            }
        }
        const float* abase = Asm + k0 * APAD + wy * 4;
#pragma unroll
        for (int kk = 0; kk < BK; kk += KSTEP) {
            float wv[CI][KSTEP];
#pragma unroll
            for (int c = 0; c < CI; c++) {
                const float* wp_ = &ws[(lane + 32 * c) * BK + kk];
                if (KSTEP == 4) {
                    float4 v = *(const float4*)wp_;
                    wv[c][0] = v.x; wv[c][1] = v.y; wv[c][2] = v.z; wv[c][3] = v.w;
                } else {
                    float2 v = *(const float2*)wp_;
                    wv[c][0] = v.x; wv[c][1] = v.y;
                }
            }
#pragma unroll
            for (int j = 0; j < KSTEP; j++) {
                ulonglong2 a = *(const ulonglong2*)(abase + (kk + j) * APAD);
#pragma unroll
                for (int c = 0; c < CI; c++) {
                    ull wp = dup2(wv[c][j]);
                    acc[0][c] = fma2(a.x, wp, acc[0][c]);
                    acc[1][c] = fma2(a.y, wp, acc[1][c]);
                }
            }
        }
        if (more) {
            __syncthreads();
#pragma unroll
            for (int i = 0; i < NLD; i++) {
                int idx = tid + 256 * i;
                if (idx < BK * N) { int kk = idx / N, c = idx - kk * N; ws[c * BK + kk] = pf[i]; }
            }
            __syncthreads();
        }
    }

#pragma unroll
    for (int c = 0; c < CI; c++) {
        int col = lane + 32 * c;
        if (col < N) {
            float bv = bg[col];
#pragma unroll
            for (int r = 0; r < 2; r++) {
                float lo, hi;
                unpack2(acc[r][c], lo, hi);
                lo += bv; hi += bv;
                if (RELU) { lo = fmaxf(lo, 0.0f); hi = fmaxf(hi, 0.0f); }
                int row = wy * 4 + 2 * r;
                if (TOGLOBAL) {
                    Gout[(size_t)row * N + col] = lo;
                    Gout[(size_t)(row + 1) * N + col] = hi;
                } else {
                    *(float2*)&Hsm[col * APAD + row] = make_float2(lo, hi);
                }
            }
        }
    }
}

__global__ __launch_bounds__(256, 3) void mlp_kernel(
    const float* __restrict__ x,
    const float* __restrict__ w1, const float* __restrict__ b1,
    const float* __restrict__ w2, const float* __restrict__ b2,
    const float* __restrict__ wl, const float* __restrict__ bl,
    float* __restrict__ logits) {
    extern __shared__ float smem[];
    const int tid = threadIdx.x;
    const int rowBase = blockIdx.x * TM;

    // stage x transposed: XsT[k][row], 32 rows x 200 k
    {
        const float4* xb = (const float4*)(x + (size_t)rowBase * D_IN);
        for (int it = tid; it < 32 * 50; it += 256) {
            int q = it >> 5, row = it & 31;
            float4 v = xb[row * 50 + q];
            float* p = smem + OFF_X + (4 * q) * APAD + row;
            p[0] = v.x; p[APAD] = v.y; p[2 * APAD] = v.z; p[3 * APAD] = v.w;
        }
    }
    layer<200, 100, 4, 20, true, false>(smem, smem + OFF_X, w1, b1, smem + OFF_H1, nullptr, tid);
    layer<100, 100, 4, 20, true, false>(smem, smem + OFF_H1, w2, b2, smem + OFF_H1, nullptr, tid);
    layer<100, 200, 7, 10, false, true>(smem, smem + OFF_H1, wl, bl, nullptr,
                                        logits + (size_t)rowBase * D_IN, tid);
}

// ---- sampler: one warp per row, 8 contiguous elems per lane (lanes 0..24) ----
__device__ __forceinline__ void load8(float* dst, const float* src, bool act) {
    if (act) {
        float4 a = *(const float4*)src;
        float4 b = *(const float4*)(src + 4);
        dst[0] = a.x; dst[1] = a.y; dst[2] = a.z; dst[3] = a.w;
        dst[4] = b.x; dst[5] = b.y; dst[6] = b.z; dst[7] = b.w;
    } else {
#pragma unroll
        for (int i = 0; i < 8; i++) dst[i] = 0.5f;
    }
}

__global__ __launch_bounds__(256, 4) void sample_kernel(
    const float* __restrict__ x, const float* __restrict__ uniform,
    const float* __restrict__ logits,
    const float* __restrict__ wo, const float* __restrict__ bo,
    float* __restrict__ preds, float* __restrict__ samples) {
    const int b = (blockIdx.x * 256 + threadIdx.x) >> 5;
    const int lane = threadIdx.x & 31;
    const bool act = lane < 25;
    const int d0 = 8 * lane;
    constexpr float EPSF = 1.1920929e-07f;

    float E[8], smp[8];
    {
        float lg[8];
        if (act) load8(lg, &logits[(size_t)b * D_IN + d0], true);
        else {
#pragma unroll
            for (int i = 0; i < 8; i++) lg[i] = -1e30f;
        }
        float m = lg[0];
#pragma unroll
        for (int i = 1; i < 8; i++) m = fmaxf(m, lg[i]);
#pragma unroll
        for (int off = 16; off > 0; off >>= 1)
            m = fmaxf(m, __shfl_xor_sync(0xffffffffu, m, off));
#pragma unroll
        for (int i = 0; i < 8; i++) {
            E[i] = act ? __expf(2.0f * (lg[i] - m)) : 0.0f;
            smp[i] = 0.0f;
        }
    }

    const float* up = uniform + (size_t)b * (K_SAMP * D_IN) + d0;
    float cu[8];
    load8(cu, up, act);

#pragma unroll
    for (int k = 0; k < K_SAMP; k++) {
        float nu[8];
        if (k < K_SAMP - 1) load8(nu, up + (k + 1) * D_IN, act);
        float s = 0.0f;
#pragma unroll
        for (int i = 0; i < 8; i++) {
            float u = fmaxf(cu[i], EPSF);
            float tl = -__logf(u);
            float xm = u - 1.0f;
            float tp = xm * fmaf(xm, fmaf(xm, -0.33333333f, 0.5f), -1.0f);
            float t = (u > 0.99f) ? tp : tl;
            float r = frcp(t);
            float w = E[i] * r * r;
            cu[i] = w;
            s += w;
        }
#pragma unroll
        for (int off = 16; off > 0; off >>= 1)
            s += __shfl_xor_sync(0xffffffffu, s, off);
        float inv = frcp(s);
#pragma unroll
        for (int i = 0; i < 8; i++) smp[i] = fmaxf(smp[i], cu[i] * inv);
        if (k < K_SAMP - 1) {
#pragma unroll
            for (int i = 0; i < 8; i++) cu[i] = nu[i];
        }
    }

    if (act) {
        *(float4*)&samples[(size_t)b * D_IN + d0] =
            make_float4(smp[0], smp[1], smp[2], smp[3]);
        *(float4*)&samples[(size_t)b * D_IN + d0 + 4] =
            make_float4(smp[4], smp[5], smp[6], smp[7]);
    }

    float p0 = 0.0f, p1 = 0.0f;
    if (act) {
        float xv[8];
        load8(xv, &x[(size_t)b * D_IN + d0], true);
#pragma unroll
        for (int i = 0; i < 8; i += 2) {
            float4 w4 = *(const float4*)&wo[(d0 + i) * 2];
            float a0 = xv[i] * smp[i], a1 = xv[i + 1] * smp[i + 1];
            p0 += a0 * w4.x + a1 * w4.z;
            p1 += a0 * w4.y + a1 * w4.w;
        }
    }
#pragma unroll
    for (int off = 16; off > 0; off >>= 1) {
        p0 += __shfl_xor_sync(0xffffffffu, p0, off);
        p1 += __shfl_xor_sync(0xffffffffu, p1, off);
    }
    if (lane == 0) {
        p0 += bo[0]; p1 += bo[1];
        float mm = fmaxf(p0, p1);
        float e0 = __expf(p0 - mm), e1 = __expf(p1 - mm);
        float is = 1.0f / (e0 + e1);
        preds[(size_t)b * 2 + 0] = e0 * is;
        preds[(size_t)b * 2 + 1] = e1 * is;
    }
}

// ---- stream/event context (host-side only; no device memory) ----
struct Ctx {
    cudaStream_t sA, sB;
    cudaEvent_t eFork, eM[NCHUNK], eJA, eJB;
    Ctx() {
        cudaStreamCreateWithFlags(&sA, cudaStreamNonBlocking);
        cudaStreamCreateWithFlags(&sB, cudaStreamNonBlocking);
        cudaEventCreateWithFlags(&eFork, cudaEventDisableTiming);
        for (int i = 0; i < NCHUNK; i++)
            cudaEventCreateWithFlags(&eM[i], cudaEventDisableTiming);
        cudaEventCreateWithFlags(&eJA, cudaEventDisableTiming);
        cudaEventCreateWithFlags(&eJB, cudaEventDisableTiming);
    }
};

extern "C" void kernel_launch(void* const* d_in, const int* in_sizes, int n_in,
                              void* d_out, int out_size) {
    static Ctx ctx;

    const float* x  = (const float*)d_in[0];
    const float* un = (const float*)d_in[1];
    const float* w1 = (const float*)d_in[2];
    const float* b1 = (const float*)d_in[3];
    const float* w2 = (const float*)d_in[4];
    const float* b2 = (const float*)d_in[5];
    const float* wl = (const float*)d_in[6];
    const float* bl = (const float*)d_in[7];
    const float* wo = (const float*)d_in[8];
    const float* bo = (const float*)d_in[9];
    float* out = (float*)d_out;

    float* lgts;
    cudaGetSymbolAddress((void**)&lgts, g_logits);

    const int smem_bytes = SMEM_FLOATS * (int)sizeof(float);  // 53440
    cudaFuncSetAttribute(mlp_kernel, cudaFuncAttributeMaxDynamicSharedMemorySize, smem_bytes);

    cudaEventRecord(ctx.eFork, 0);
    cudaStreamWaitEvent(ctx.sA, ctx.eFork, 0);
    cudaStreamWaitEvent(ctx.sB, ctx.eFork, 0);

    for (int c = 0; c < NCHUNK; c++) {
        const size_t ro = (size_t)c * CHUNK;
        mlp_kernel<<<CHUNK / TM, 256, smem_bytes, ctx.sA>>>(
            x + ro * D_IN, w1, b1, w2, b2, wl, bl, lgts + ro * D_IN);
        cudaEventRecord(ctx.eM[c], ctx.sA);
        cudaStreamWaitEvent(ctx.sB, ctx.eM[c], 0);
        sample_kernel<<<CHUNK / 8, 256, 0, ctx.sB>>>(
            x + ro * D_IN, un + ro * (K_SAMP * D_IN), lgts + ro * D_IN, wo, bo,
            out + ro * 2, out + (size_t)B_ROWS * 2 + ro * D_IN);
    }

    cudaEventRecord(ctx.eJA, ctx.sA);
    cudaStreamWaitEvent(0, ctx.eJA, 0);
    cudaEventRecord(ctx.eJB, ctx.sB);
    cudaStreamWaitEvent(0, ctx.eJB, 0);
}